// round 3
// baseline (speedup 1.0000x reference)
#include <cuda_runtime.h>

#define BB 8
#define LL 2048
#define DD 256
#define MM (BB*LL)

// ---------------- scratch (device globals; no runtime allocation) ----------
__device__ float g_xc[MM*DD];   // conv output (GEMM1 input)
__device__ float g_y [MM*DD];   // proj output (masked)
__device__ float g_z [MM*DD];   // weighted mix (GEMM2 input)
__device__ float g_t [MM];      // per-position score scalar
__device__ float g_w [MM*4];    // softmax-combined weights (w_x, w2', w3', w4')
__device__ int   g_len[BB];

// ---------------- K0: sequence lengths ------------------------------------
__global__ void k_len(const int* __restrict__ seq){
  __shared__ int cnt;
  if(threadIdx.x==0) cnt=0;
  __syncthreads();
  int c=0;
  for(int l=threadIdx.x;l<LL;l+=256) c += (seq[blockIdx.x*LL+l]!=0);
  #pragma unroll
  for(int o=16;o>0;o>>=1) c += __shfl_xor_sync(0xffffffffu,c,o);
  if((threadIdx.x&31)==0) atomicAdd(&cnt,c);
  __syncthreads();
  if(threadIdx.x==0) g_len[blockIdx.x]=cnt;
}

// ---------------- K1: embed (*16) + depthwise conv(4) + conv bias ----------
__global__ void k_buildxc(const int* __restrict__ seq,
                          const float* __restrict__ emb,
                          const float* __restrict__ cw,
                          const float* __restrict__ cb){
  int idx = blockIdx.x*256 + threadIdx.x;       // over MM*64 float4 units
  int m  = idx >> 6;
  int d4 = (idx & 63) << 2;
  int l  = m & (LL-1);
  float4 ek[4];
  #pragma unroll
  for(int k=0;k<4;k++){
    if(l + k < LL){
      int tok = seq[m + k];                     // pad token 0 -> emb[0] (matches ref)
      float4 e = *(const float4*)&emb[tok*DD + d4];
      ek[k] = make_float4(e.x*16.f, e.y*16.f, e.z*16.f, e.w*16.f);
    } else {
      ek[k] = make_float4(0.f,0.f,0.f,0.f);     // end-of-array zero padding
    }
  }
  float4 o;
  float* op = &o.x;
  #pragma unroll
  for(int j=0;j<4;j++){
    float4 w = *(const float4*)&cw[(d4+j)*4];   // conv_w[d][0][0..3]
    float v = cb[d4+j];
    v += w.x * (&ek[0].x)[j];
    v += w.y * (&ek[1].x)[j];
    v += w.z * (&ek[2].x)[j];
    v += w.w * (&ek[3].x)[j];
    op[j] = v;
  }
  *(float4*)&g_xc[m*DD + d4] = o;
}

// ---------------- SGEMM: C[m,n] = sum_k A[m,k]*W[n,k] + bias[n], epilogues -
// epi=0: mask rows with seq==0 to zero       (proj)
// epi=1: C = A[m,n] + relu(acc + bias[n])    (FF residual; A doubles as z)
__global__ __launch_bounds__(256,2) void k_sgemm(
    const float* __restrict__ A, const float* __restrict__ W,
    const float* __restrict__ bias, const int* __restrict__ seq,
    float* __restrict__ C, int epi)
{
  __shared__ float As[16][128];
  __shared__ float Bs[16][128];
  const int m0 = blockIdx.x*128, n0 = blockIdx.y*128;
  const int tid = threadIdx.x;
  const int tm = (tid>>4)<<3, tn = (tid&15)<<3;
  float acc[8][8];
  #pragma unroll
  for(int i=0;i<8;i++)
    #pragma unroll
    for(int j=0;j<8;j++) acc[i][j]=0.f;

  for(int k0=0;k0<DD;k0+=16){
    #pragma unroll
    for(int i=0;i<2;i++){
      int f = (tid<<1)+i;
      int r = f>>2, kq = (f&3)<<2;
      float4 va = *(const float4*)&A[(m0+r)*DD + k0 + kq];
      As[kq+0][r]=va.x; As[kq+1][r]=va.y; As[kq+2][r]=va.z; As[kq+3][r]=va.w;
      float4 vb = *(const float4*)&W[(n0+r)*DD + k0 + kq];
      Bs[kq+0][r]=vb.x; Bs[kq+1][r]=vb.y; Bs[kq+2][r]=vb.z; Bs[kq+3][r]=vb.w;
    }
    __syncthreads();
    #pragma unroll
    for(int kk=0;kk<16;kk++){
      float a[8], b[8];
      *(float4*)&a[0] = *(const float4*)&As[kk][tm];
      *(float4*)&a[4] = *(const float4*)&As[kk][tm+4];
      *(float4*)&b[0] = *(const float4*)&Bs[kk][tn];
      *(float4*)&b[4] = *(const float4*)&Bs[kk][tn+4];
      #pragma unroll
      for(int i=0;i<8;i++)
        #pragma unroll
        for(int j=0;j<8;j++) acc[i][j] += a[i]*b[j];
    }
    __syncthreads();
  }

  #pragma unroll
  for(int i=0;i<8;i++){
    int m = m0+tm+i;
    bool pad = (epi==0) && (seq[m]==0);
    #pragma unroll
    for(int jq=0;jq<2;jq++){
      int nb = n0+tn+jq*4;
      float4 o; float* op=&o.x;
      if(epi==0){
        #pragma unroll
        for(int j=0;j<4;j++) op[j] = pad ? 0.f : (acc[i][jq*4+j] + bias[nb+j]);
      } else {
        float4 zv = *(const float4*)&A[m*DD + nb];
        const float* zp=&zv.x;
        #pragma unroll
        for(int j=0;j<4;j++) op[j] = zp[j] + fmaxf(acc[i][jq*4+j] + bias[nb+j], 0.f);
      }
      *(float4*)&C[m*DD + nb] = o;
    }
  }
}

// ---------------- K3: t[m] = y[m] . score_w + score_b ----------------------
__global__ void k_dot(const float* __restrict__ y,
                      const float* __restrict__ sw,
                      const float* __restrict__ sb){
  __shared__ float s[DD];
  s[threadIdx.x] = sw[threadIdx.x];
  __syncthreads();
  int w = threadIdx.x>>5, lane = threadIdx.x&31;
  int m = blockIdx.x*8 + w;
  const float* row = &y[m*DD];
  int base = lane*8;
  float4 a0 = *(const float4*)&row[base];
  float4 a1 = *(const float4*)&row[base+4];
  float4 b0 = *(const float4*)&s[base];
  float4 b1 = *(const float4*)&s[base+4];
  float acc = a0.x*b0.x + a0.y*b0.y + a0.z*b0.z + a0.w*b0.w
            + a1.x*b1.x + a1.y*b1.y + a1.z*b1.z + a1.w*b1.w;
  #pragma unroll
  for(int o=16;o>0;o>>=1) acc += __shfl_xor_sync(0xffffffffu,acc,o);
  if(lane==0) g_t[m] = acc + sb[0];
}

// ---------------- K4: collapsed softmax over the 10 block scores -----------
// scores = [t0, m2,m2, m3,m3,m3, m4,m4,m4,m4]; store combined weights
// w[0]=e0/Z, w[si+1]=(si+2)*e_s/(Z*cnt_s)  (so K5 only needs group SUMS)
__global__ void k_weights(){
  int m = blockIdx.x*256 + threadIdx.x;
  int b = m >> 11, l = m & (LL-1);
  int len = g_len[b];
  float4 w = make_float4(0.f,0.f,0.f,0.f);
  if(l < len){
    const float* tb = &g_t[b*LL];
    float t0 = tb[l];
    float sc[3], invc[3];
    #pragma unroll
    for(int si=0;si<3;si++){
      int s = si+2;
      int a = (l/s)*s;
      int e = min(a+s, len);
      float sum=0.f;
      for(int p=a;p<e;p++) sum += tb[p];
      float c = (float)(e-a);
      sc[si] = sum / c;
      invc[si] = 1.f/c;
    }
    float mx = fmaxf(fmaxf(t0,sc[0]),fmaxf(sc[1],sc[2]));
    float e0=expf(t0-mx), e2=expf(sc[0]-mx), e3=expf(sc[1]-mx), e4=expf(sc[2]-mx);
    float inv = 1.f/(e0 + 2.f*e2 + 3.f*e3 + 4.f*e4);
    w = make_float4(e0*inv, 2.f*e2*inv*invc[0], 3.f*e3*inv*invc[1], 4.f*e4*inv*invc[2]);
  }
  *(float4*)&g_w[m*4] = w;
}

// ---------------- K5: z = w_x*y + sum_s w_s' * (group sum of y) ------------
__global__ void k_mix(){
  int idx = blockIdx.x*256 + threadIdx.x;       // MM*64 float4 units
  int m  = idx >> 6;
  int d4 = (idx & 63) << 2;
  int b = m >> 11, l = m & (LL-1);
  int len = g_len[b];
  float4 o = make_float4(0.f,0.f,0.f,0.f);
  if(l < len){
    float4 w = *(const float4*)&g_w[m*4];
    const float* yb = &g_y[(size_t)(b*LL)*DD + d4];
    float4 v = *(const float4*)&yb[(size_t)l*DD];
    o.x = w.x*v.x; o.y = w.x*v.y; o.z = w.x*v.z; o.w = w.x*v.w;
    float ws[3] = {w.y, w.z, w.w};
    #pragma unroll
    for(int si=0;si<3;si++){
      int s = si+2;
      int a = (l/s)*s;
      int e = min(a+s, len);
      float4 sum = make_float4(0.f,0.f,0.f,0.f);
      for(int p=a;p<e;p++){
        float4 u = *(const float4*)&yb[(size_t)p*DD];
        sum.x+=u.x; sum.y+=u.y; sum.z+=u.z; sum.w+=u.w;
      }
      o.x += ws[si]*sum.x; o.y += ws[si]*sum.y;
      o.z += ws[si]*sum.z; o.w += ws[si]*sum.w;
    }
  }
  *(float4*)&g_z[m*DD + d4] = o;
}

// ---------------- launch ----------------------------------------------------
extern "C" void kernel_launch(void* const* d_in, const int* in_sizes, int n_in,
                              void* d_out, int out_size){
  const int*   seq = (const int*)  d_in[0];
  // d_in[1] = group_id: unused (reconstructed analytically from sizes/lens)
  const float* emb = (const float*)d_in[2];
  const float* cw  = (const float*)d_in[3];
  const float* cb  = (const float*)d_in[4];
  const float* pw  = (const float*)d_in[5];
  const float* pb  = (const float*)d_in[6];
  const float* sw  = (const float*)d_in[7];
  const float* sb  = (const float*)d_in[8];
  const float* fw  = (const float*)d_in[9];
  const float* fb  = (const float*)d_in[10];
  float* out = (float*)d_out;

  float *xc, *y, *z;
  cudaGetSymbolAddress((void**)&xc, g_xc);
  cudaGetSymbolAddress((void**)&y,  g_y);
  cudaGetSymbolAddress((void**)&z,  g_z);

  k_len    <<<BB, 256>>>(seq);
  k_buildxc<<<MM*64/256, 256>>>(seq, emb, cw, cb);
  k_sgemm  <<<dim3(MM/128, DD/128), 256>>>(xc, pw, pb, seq, y, 0);
  k_dot    <<<MM/8, 256>>>(y, sw, sb);
  k_weights<<<MM/256, 256>>>();
  k_mix    <<<MM*64/256, 256>>>();
  k_sgemm  <<<dim3(MM/128, DD/128), 256>>>(z, fw, fb, seq, out, 1);
}

// round 6
// speedup vs baseline: 1.7052x; 1.7052x over previous
#include <cuda_runtime.h>
#include <cuda_bf16.h>
#include <cstdint>

#define BB 8
#define LL 2048
#define DD 256
#define MM (BB*LL)

// ---------------- scratch (device globals; no runtime allocation) ----------
__device__ float g_xc[MM*DD];   // conv output (GEMM1 input)
__device__ float g_y [MM*DD];   // proj output (masked)
__device__ float g_z [MM*DD];   // weighted mix (GEMM2 input)
__device__ float g_t [MM];      // per-position score scalar
__device__ float g_w [MM*4];    // softmax-combined weights
__device__ int   g_len[BB];

// ---------------- K0: sequence lengths ------------------------------------
__global__ void k_len(const int* __restrict__ seq){
  __shared__ int cnt;
  if(threadIdx.x==0) cnt=0;
  __syncthreads();
  int c=0;
  for(int l=threadIdx.x;l<LL;l+=256) c += (seq[blockIdx.x*LL+l]!=0);
  #pragma unroll
  for(int o=16;o>0;o>>=1) c += __shfl_xor_sync(0xffffffffu,c,o);
  if((threadIdx.x&31)==0) atomicAdd(&cnt,c);
  __syncthreads();
  if(threadIdx.x==0) g_len[blockIdx.x]=cnt;
}

// ---------------- K1: embed (*16) + depthwise conv(4) + conv bias ----------
__global__ void k_buildxc(const int* __restrict__ seq,
                          const float* __restrict__ emb,
                          const float* __restrict__ cw,
                          const float* __restrict__ cb){
  int idx = blockIdx.x*256 + threadIdx.x;
  int m  = idx >> 6;
  int d4 = (idx & 63) << 2;
  int l  = m & (LL-1);
  float4 ek[4];
  #pragma unroll
  for(int k=0;k<4;k++){
    if(l + k < LL){
      int tok = seq[m + k];
      float4 e = *(const float4*)&emb[tok*DD + d4];
      ek[k] = make_float4(e.x*16.f, e.y*16.f, e.z*16.f, e.w*16.f);
    } else {
      ek[k] = make_float4(0.f,0.f,0.f,0.f);
    }
  }
  float4 o; float* op = &o.x;
  #pragma unroll
  for(int j=0;j<4;j++){
    float4 w = *(const float4*)&cw[(d4+j)*4];
    float v = cb[d4+j];
    v += w.x * (&ek[0].x)[j];
    v += w.y * (&ek[1].x)[j];
    v += w.z * (&ek[2].x)[j];
    v += w.w * (&ek[3].x)[j];
    op[j] = v;
  }
  *(float4*)&g_xc[m*DD + d4] = o;
}

// ============== warp-MMA GEMM: C[16384,256] = A @ W^T (+epilogue) ==========
// bf16 3-term split accumulated in fp32: Ahi*Whi + Alo*Whi + Ahi*Wlo.
// CTA tile 128x128, grid (128,2), 256 thr, warp tile 64x32 (warps 2m x 4n).
// epi=0 (proj): C = pad ? 0 : acc+bias
// epi=1 (ff):   C = A[m,n] + relu(acc+bias)
#define PK 72                       // smem pitch in bf16 elements
#define PKW 36                      // pitch in b32 words
#define TILE_HALFS (128*PK)         // per matrix-part per chunk
#define SMEM_BYTES (4*TILE_HALFS*2) // Ahi,Alo,Whi,Wlo = 73728

static __device__ __forceinline__ uint32_t bfp2(float x0, float x1){
  uint32_t b0 = (uint32_t)__bfloat16_as_ushort(__float2bfloat16_rn(x0));
  uint32_t b1 = (uint32_t)__bfloat16_as_ushort(__float2bfloat16_rn(x1));
  return b0 | (b1<<16);
}

#define MMA_BF16(c, A0,A1,A2,A3, B0,B1) \
  asm volatile("mma.sync.aligned.m16n8k16.row.col.f32.bf16.bf16.f32 " \
    "{%0,%1,%2,%3}, {%4,%5,%6,%7}, {%8,%9}, {%0,%1,%2,%3};" \
    : "+f"((c)[0]), "+f"((c)[1]), "+f"((c)[2]), "+f"((c)[3]) \
    : "r"(A0), "r"(A1), "r"(A2), "r"(A3), "r"(B0), "r"(B1))

__global__ __launch_bounds__(256,2) void k_tgemm(
    const float* __restrict__ A, const float* __restrict__ W,
    const float* __restrict__ bias, const int* __restrict__ seq,
    float* __restrict__ C, int epi)
{
  extern __shared__ __align__(16) char smraw[];
  __nv_bfloat16* sAh = (__nv_bfloat16*)smraw;
  __nv_bfloat16* sAl = sAh + TILE_HALFS;
  __nv_bfloat16* sWh = sAl + TILE_HALFS;
  __nv_bfloat16* sWl = sWh + TILE_HALFS;
  const uint32_t* wAh = (const uint32_t*)sAh;
  const uint32_t* wAl = (const uint32_t*)sAl;
  const uint32_t* wWh = (const uint32_t*)sWh;
  const uint32_t* wWl = (const uint32_t*)sWl;

  const int tid = threadIdx.x;
  const int wid = tid>>5, lane = tid&31;
  const int g = lane>>2, t = lane&3;
  const int wm = wid & 1, wn = wid >> 1;       // 2 x 4 warp grid
  const int m0 = blockIdx.x*128, n0 = blockIdx.y*128;

  float acc[4][4][4];
  #pragma unroll
  for(int i=0;i<4;i++)
    #pragma unroll
    for(int j=0;j<4;j++)
      #pragma unroll
      for(int q=0;q<4;q++) acc[i][j][q]=0.f;

  for(int c=0;c<4;c++){
    const int k0 = c*64;
    if(c) __syncthreads();                      // protect buffer reuse
    // ---- load+convert chunk: A[128x64] and W[128x64] fp32 -> hi/lo bf16 ---
    #pragma unroll
    for(int u=tid; u<2*128*16; u+=256){
      int isW = u >= 128*16;
      int v2 = isW ? (u - 128*16) : u;
      int r = v2>>4, q4 = (v2&15)<<2;
      const float* G = isW ? W : A;
      int row = (isW ? n0 : m0) + r;
      float4 v = *(const float4*)&G[(size_t)row*DD + k0 + q4];
      float h0 = __bfloat162float(__float2bfloat16_rn(v.x));
      float h1 = __bfloat162float(__float2bfloat16_rn(v.y));
      float h2 = __bfloat162float(__float2bfloat16_rn(v.z));
      float h3 = __bfloat162float(__float2bfloat16_rn(v.w));
      uint2 H = make_uint2(bfp2(h0,h1), bfp2(h2,h3));
      uint2 L = make_uint2(bfp2(v.x-h0, v.y-h1), bfp2(v.z-h2, v.w-h3));
      __nv_bfloat16* dh = isW ? sWh : sAh;
      __nv_bfloat16* dl = isW ? sWl : sAl;
      *(uint2*)&dh[r*PK + q4] = H;
      *(uint2*)&dl[r*PK + q4] = L;
    }
    __syncthreads();
    // ---- compute: 4 k16 steps ----
    #pragma unroll
    for(int ks=0; ks<4; ks++){
      const int kw = ks*8;                      // word offset within chunk
      uint32_t ah[4][4], al[4][4];
      #pragma unroll
      for(int mt=0;mt<4;mt++){
        int r0 = wm*64 + mt*16 + g;
        int b0i = r0*PKW + kw + t;
        int b8i = (r0+8)*PKW + kw + t;
        ah[mt][0]=wAh[b0i];   ah[mt][1]=wAh[b8i];
        ah[mt][2]=wAh[b0i+4]; ah[mt][3]=wAh[b8i+4];
        al[mt][0]=wAl[b0i];   al[mt][1]=wAl[b8i];
        al[mt][2]=wAl[b0i+4]; al[mt][3]=wAl[b8i+4];
      }
      #pragma unroll
      for(int nt=0;nt<4;nt++){
        int nr = wn*32 + nt*8 + g;
        int bi = nr*PKW + kw + t;
        uint32_t bh0=wWh[bi], bh1=wWh[bi+4];
        uint32_t bl0=wWl[bi], bl1=wWl[bi+4];
        #pragma unroll
        for(int mt=0;mt<4;mt++){
          MMA_BF16(acc[mt][nt], ah[mt][0],ah[mt][1],ah[mt][2],ah[mt][3], bh0,bh1);
          MMA_BF16(acc[mt][nt], al[mt][0],al[mt][1],al[mt][2],al[mt][3], bh0,bh1);
          MMA_BF16(acc[mt][nt], ah[mt][0],ah[mt][1],ah[mt][2],ah[mt][3], bl0,bl1);
        }
      }
    }
  }

  // ---- epilogue ----
  #pragma unroll
  for(int mt=0;mt<4;mt++){
    int row = m0 + wm*64 + mt*16 + g;
    bool p0=false, p1=false;
    if(epi==0){ p0 = (seq[row]==0); p1 = (seq[row+8]==0); }
    #pragma unroll
    for(int nt=0;nt<4;nt++){
      int col = n0 + wn*32 + nt*8 + 2*t;
      float b0v = bias[col], b1v = bias[col+1];
      float* cc = acc[mt][nt];
      float2 o0, o1;
      if(epi==0){
        o0 = p0 ? make_float2(0.f,0.f) : make_float2(cc[0]+b0v, cc[1]+b1v);
        o1 = p1 ? make_float2(0.f,0.f) : make_float2(cc[2]+b0v, cc[3]+b1v);
      } else {
        float2 z0 = *(const float2*)&A[(size_t)row*DD + col];
        float2 z1 = *(const float2*)&A[(size_t)(row+8)*DD + col];
        o0 = make_float2(z0.x + fmaxf(cc[0]+b0v,0.f), z0.y + fmaxf(cc[1]+b1v,0.f));
        o1 = make_float2(z1.x + fmaxf(cc[2]+b0v,0.f), z1.y + fmaxf(cc[3]+b1v,0.f));
      }
      *(float2*)&C[(size_t)row*DD + col] = o0;
      *(float2*)&C[(size_t)(row+8)*DD + col] = o1;
    }
  }
}

// ---------------- K3: t[m] = y[m] . score_w + score_b ----------------------
__global__ void k_dot(const float* __restrict__ y,
                      const float* __restrict__ sw,
                      const float* __restrict__ sb){
  __shared__ float s[DD];
  s[threadIdx.x] = sw[threadIdx.x];
  __syncthreads();
  int w = threadIdx.x>>5, lane = threadIdx.x&31;
  int m = blockIdx.x*8 + w;
  const float* row = &y[m*DD];
  int base = lane*8;
  float4 a0 = *(const float4*)&row[base];
  float4 a1 = *(const float4*)&row[base+4];
  float4 b0 = *(const float4*)&s[base];
  float4 b1 = *(const float4*)&s[base+4];
  float acc = a0.x*b0.x + a0.y*b0.y + a0.z*b0.z + a0.w*b0.w
            + a1.x*b1.x + a1.y*b1.y + a1.z*b1.z + a1.w*b1.w;
  #pragma unroll
  for(int o=16;o>0;o>>=1) acc += __shfl_xor_sync(0xffffffffu,acc,o);
  if(lane==0) g_t[m] = acc + sb[0];
}

// ---------------- K4: collapsed softmax over the 10 block scores -----------
__global__ void k_weights(){
  int m = blockIdx.x*256 + threadIdx.x;
  int b = m >> 11, l = m & (LL-1);
  int len = g_len[b];
  float4 w = make_float4(0.f,0.f,0.f,0.f);
  if(l < len){
    const float* tb = &g_t[b*LL];
    float t0 = tb[l];
    float sc[3], invc[3];
    #pragma unroll
    for(int si=0;si<3;si++){
      int s = si+2;
      int a = (l/s)*s;
      int e = min(a+s, len);
      float sum=0.f;
      for(int p=a;p<e;p++) sum += tb[p];
      float c = (float)(e-a);
      sc[si] = sum / c;
      invc[si] = 1.f/c;
    }
    float mx = fmaxf(fmaxf(t0,sc[0]),fmaxf(sc[1],sc[2]));
    float e0=expf(t0-mx), e2=expf(sc[0]-mx), e3=expf(sc[1]-mx), e4=expf(sc[2]-mx);
    float inv = 1.f/(e0 + 2.f*e2 + 3.f*e3 + 4.f*e4);
    w = make_float4(e0*inv, 2.f*e2*inv*invc[0], 3.f*e3*inv*invc[1], 4.f*e4*inv*invc[2]);
  }
  *(float4*)&g_w[m*4] = w;
}

// ---------------- K5: z = w_x*y + sum_s w_s' * (group sum of y) ------------
__global__ void k_mix(){
  int idx = blockIdx.x*256 + threadIdx.x;
  int m  = idx >> 6;
  int d4 = (idx & 63) << 2;
  int b = m >> 11, l = m & (LL-1);
  int len = g_len[b];
  float4 o = make_float4(0.f,0.f,0.f,0.f);
  if(l < len){
    float4 w = *(const float4*)&g_w[m*4];
    const float* yb = &g_y[(size_t)(b*LL)*DD + d4];
    float4 v = *(const float4*)&yb[(size_t)l*DD];
    o.x = w.x*v.x; o.y = w.x*v.y; o.z = w.x*v.z; o.w = w.x*v.w;
    float ws[3] = {w.y, w.z, w.w};
    #pragma unroll
    for(int si=0;si<3;si++){
      int s = si+2;
      int a = (l/s)*s;
      int e = min(a+s, len);
      float4 sum = make_float4(0.f,0.f,0.f,0.f);
      for(int p=a;p<e;p++){
        float4 u = *(const float4*)&yb[(size_t)p*DD];
        sum.x+=u.x; sum.y+=u.y; sum.z+=u.z; sum.w+=u.w;
      }
      o.x += ws[si]*sum.x; o.y += ws[si]*sum.y;
      o.z += ws[si]*sum.z; o.w += ws[si]*sum.w;
    }
  }
  *(float4*)&g_z[m*DD + d4] = o;
}

// ---------------- launch ----------------------------------------------------
extern "C" void kernel_launch(void* const* d_in, const int* in_sizes, int n_in,
                              void* d_out, int out_size){
  const int*   seq = (const int*)  d_in[0];
  const float* emb = (const float*)d_in[2];
  const float* cw  = (const float*)d_in[3];
  const float* cb  = (const float*)d_in[4];
  const float* pw  = (const float*)d_in[5];
  const float* pb  = (const float*)d_in[6];
  const float* sw  = (const float*)d_in[7];
  const float* sb  = (const float*)d_in[8];
  const float* fw  = (const float*)d_in[9];
  const float* fb  = (const float*)d_in[10];
  float* out = (float*)d_out;

  float *xc, *y, *z;
  cudaGetSymbolAddress((void**)&xc, g_xc);
  cudaGetSymbolAddress((void**)&y,  g_y);
  cudaGetSymbolAddress((void**)&z,  g_z);

  cudaFuncSetAttribute(k_tgemm, cudaFuncAttributeMaxDynamicSharedMemorySize, SMEM_BYTES);

  k_len    <<<BB, 256>>>(seq);
  k_buildxc<<<MM*64/256, 256>>>(seq, emb, cw, cb);
  k_tgemm  <<<dim3(MM/128, 2), 256, SMEM_BYTES>>>(xc, pw, pb, seq, y, 0);
  k_dot    <<<MM/8, 256>>>(y, sw, sb);
  k_weights<<<MM/256, 256>>>();
  k_mix    <<<MM*64/256, 256>>>();
  k_tgemm  <<<dim3(MM/128, 2), 256, SMEM_BYTES>>>(z, fw, fb, seq, out, 1);
}

// round 7
// speedup vs baseline: 1.8645x; 1.0934x over previous
#include <cuda_runtime.h>
#include <cuda_bf16.h>
#include <cstdint>

#define BB 8
#define LL 2048
#define DD 256
#define MM (BB*LL)
#define NCH 171   // ceil(LL/12)

// ---------------- scratch (device globals; no runtime allocation) ----------
__device__ __nv_bfloat16 g_xch[MM*DD], g_xcl[MM*DD];  // conv out, hi/lo planes
__device__ __nv_bfloat16 g_yh [MM*DD], g_yl [MM*DD];  // proj out (masked)
__device__ __nv_bfloat16 g_zh [MM*DD], g_zl [MM*DD];  // weighted mix
__device__ float g_tp[2*MM];    // per-row partial score dots (2 N-halves)
__device__ float g_w [MM*4];    // softmax-combined weights
__device__ int   g_len[BB];

// ---------------- helpers ---------------------------------------------------
static __device__ __forceinline__ uint32_t bfp2(float x0, float x1){
  uint32_t b0 = (uint32_t)__bfloat16_as_ushort(__float2bfloat16_rn(x0));
  uint32_t b1 = (uint32_t)__bfloat16_as_ushort(__float2bfloat16_rn(x1));
  return b0 | (b1<<16);
}
static __device__ __forceinline__ float2 unpk(uint32_t u){
  __nv_bfloat162 h = *reinterpret_cast<__nv_bfloat162*>(&u);
  return __bfloat1622float2(h);
}
// split 4 floats into hi/lo bf16 pairs
static __device__ __forceinline__ void split4(const float* v, uint2& H, uint2& L){
  float h0 = __bfloat162float(__float2bfloat16_rn(v[0]));
  float h1 = __bfloat162float(__float2bfloat16_rn(v[1]));
  float h2 = __bfloat162float(__float2bfloat16_rn(v[2]));
  float h3 = __bfloat162float(__float2bfloat16_rn(v[3]));
  H = make_uint2(bfp2(h0,h1), bfp2(h2,h3));
  L = make_uint2(bfp2(v[0]-h0, v[1]-h1), bfp2(v[2]-h2, v[3]-h3));
}
// load 4 floats = hi+lo from planes at half-offset off (4-aligned)
static __device__ __forceinline__ void load4(const __nv_bfloat16* hi,
    const __nv_bfloat16* lo, size_t off, float* v){
  uint2 H = *(const uint2*)(hi+off);
  uint2 L = *(const uint2*)(lo+off);
  float2 a0=unpk(H.x), a1=unpk(H.y), b0=unpk(L.x), b1=unpk(L.y);
  v[0]=a0.x+b0.x; v[1]=a0.y+b0.y; v[2]=a1.x+b1.x; v[3]=a1.y+b1.y;
}

// ---------------- K0: sequence lengths ------------------------------------
__global__ void k_len(const int* __restrict__ seq){
  __shared__ int cnt;
  if(threadIdx.x==0) cnt=0;
  __syncthreads();
  int c=0;
  for(int l=threadIdx.x;l<LL;l+=256) c += (seq[blockIdx.x*LL+l]!=0);
  #pragma unroll
  for(int o=16;o>0;o>>=1) c += __shfl_xor_sync(0xffffffffu,c,o);
  if((threadIdx.x&31)==0) atomicAdd(&cnt,c);
  __syncthreads();
  if(threadIdx.x==0) g_len[blockIdx.x]=cnt;
}

// ---------------- K1: embed(*16) + depthwise conv(4); 4 rows/thread --------
__global__ void k_buildxc(const int* __restrict__ seq,
                          const float* __restrict__ emb,
                          const float* __restrict__ cw,
                          const float* __restrict__ cb){
  int idx = blockIdx.x*256 + threadIdx.x;
  int cid = idx >> 6;                  // 4-row chunk id (0..MM/4-1)
  int d4  = (idx & 63) << 2;
  int m0r = cid << 2;
  int l   = m0r & (LL-1);
  float e[7][4];
  #pragma unroll
  for(int k=0;k<7;k++){
    if(l + k < LL){
      int tok = seq[m0r + k];
      float4 t = *(const float4*)&emb[tok*DD + d4];
      e[k][0]=t.x*16.f; e[k][1]=t.y*16.f; e[k][2]=t.z*16.f; e[k][3]=t.w*16.f;
    } else {
      e[k][0]=e[k][1]=e[k][2]=e[k][3]=0.f;
    }
  }
  float4 cwv[4]; float cbv[4];
  #pragma unroll
  for(int i=0;i<4;i++){ cwv[i] = *(const float4*)&cw[(d4+i)*4]; cbv[i]=cb[d4+i]; }
  #pragma unroll
  for(int j=0;j<4;j++){
    float o[4];
    #pragma unroll
    for(int i=0;i<4;i++)
      o[i] = cbv[i] + cwv[i].x*e[j][i] + cwv[i].y*e[j+1][i]
                    + cwv[i].z*e[j+2][i] + cwv[i].w*e[j+3][i];
    uint2 H,L; split4(o,H,L);
    size_t off = (size_t)(m0r+j)*DD + d4;
    *(uint2*)(g_xch+off) = H;
    *(uint2*)(g_xcl+off) = L;
  }
}

// ============== warp-MMA GEMM: C[16384,256] = A @ W^T (+epilogue) ==========
// A pre-split hi/lo bf16 planes; W fp32 converted in-kernel.
// 3-term: Ahi*Whi + Alo*Whi + Ahi*Wlo, fp32 accum.
// epi=0 (proj): y(hi/lo) = pad?0:acc+bias; per-row partial dot -> g_tp
// epi=1 (ff):   Cf = (zh+zl) + relu(acc+bias)
#define PK 72
#define PKW 36
#define TILE_HALFS (128*PK)
#define SMEM_BYTES (4*TILE_HALFS*2 + 2048)   // tiles + t_s[512]

#define MMA_BF16(c, A0,A1,A2,A3, B0,B1) \
  asm volatile("mma.sync.aligned.m16n8k16.row.col.f32.bf16.bf16.f32 " \
    "{%0,%1,%2,%3}, {%4,%5,%6,%7}, {%8,%9}, {%0,%1,%2,%3};" \
    : "+f"((c)[0]), "+f"((c)[1]), "+f"((c)[2]), "+f"((c)[3]) \
    : "r"(A0), "r"(A1), "r"(A2), "r"(A3), "r"(B0), "r"(B1))

__global__ __launch_bounds__(256,2) void k_tgemm(
    const __nv_bfloat16* __restrict__ Ah, const __nv_bfloat16* __restrict__ Al,
    const float* __restrict__ W, const float* __restrict__ bias,
    const int* __restrict__ seq,
    __nv_bfloat16* __restrict__ Ch, __nv_bfloat16* __restrict__ Cl,
    float* __restrict__ Cf, const float* __restrict__ swv, int epi)
{
  extern __shared__ __align__(16) char smraw[];
  __nv_bfloat16* sAh = (__nv_bfloat16*)smraw;
  __nv_bfloat16* sAl = sAh + TILE_HALFS;
  __nv_bfloat16* sWh = sAl + TILE_HALFS;
  __nv_bfloat16* sWl = sWh + TILE_HALFS;
  float* t_s = (float*)(smraw + 4*TILE_HALFS*2);
  const uint32_t* wAh = (const uint32_t*)sAh;
  const uint32_t* wAl = (const uint32_t*)sAl;
  const uint32_t* wWh = (const uint32_t*)sWh;
  const uint32_t* wWl = (const uint32_t*)sWl;

  const int tid = threadIdx.x;
  const int wid = tid>>5, lane = tid&31;
  const int g = lane>>2, t = lane&3;
  const int wm = wid & 1, wn = wid >> 1;
  const int m0 = blockIdx.x*128, n0 = blockIdx.y*128;

  float acc[4][4][4];
  #pragma unroll
  for(int i=0;i<4;i++)
    #pragma unroll
    for(int j=0;j<4;j++)
      #pragma unroll
      for(int q=0;q<4;q++) acc[i][j][q]=0.f;

  for(int c4=0;c4<4;c4++){
    const int k0 = c4*64;
    if(c4) __syncthreads();
    // A planes: straight uint4 copies; W: fp32 -> hi/lo convert
    #pragma unroll
    for(int u=tid; u<4096; u+=256){
      if(u < 2048){
        int plane = u>>10;
        int v = u & 1023;
        int r = v>>3, q = v&7;
        const __nv_bfloat16* src = plane ? Al : Ah;
        uint4 d = *(const uint4*)(src + (size_t)(m0+r)*DD + k0 + q*8);
        __nv_bfloat16* dst = plane ? sAl : sAh;
        *(uint4*)&dst[r*PK + q*8] = d;
      } else {
        int v = u - 2048;
        int r = v>>4, q4 = (v&15)<<2;
        float4 vv = *(const float4*)&W[(size_t)(n0+r)*DD + k0 + q4];
        float f[4] = {vv.x, vv.y, vv.z, vv.w};
        uint2 H,L; split4(f,H,L);
        *(uint2*)&sWh[r*PK + q4] = H;
        *(uint2*)&sWl[r*PK + q4] = L;
      }
    }
    __syncthreads();
    #pragma unroll
    for(int ks=0; ks<4; ks++){
      const int kw = ks*8;
      uint32_t ah[4][4], al[4][4];
      #pragma unroll
      for(int mt=0;mt<4;mt++){
        int r0 = wm*64 + mt*16 + g;
        int b0i = r0*PKW + kw + t;
        int b8i = (r0+8)*PKW + kw + t;
        ah[mt][0]=wAh[b0i];   ah[mt][1]=wAh[b8i];
        ah[mt][2]=wAh[b0i+4]; ah[mt][3]=wAh[b8i+4];
        al[mt][0]=wAl[b0i];   al[mt][1]=wAl[b8i];
        al[mt][2]=wAl[b0i+4]; al[mt][3]=wAl[b8i+4];
      }
      #pragma unroll
      for(int nt=0;nt<4;nt++){
        int nr = wn*32 + nt*8 + g;
        int bi = nr*PKW + kw + t;
        uint32_t bh0=wWh[bi], bh1=wWh[bi+4];
        uint32_t bl0=wWl[bi], bl1=wWl[bi+4];
        #pragma unroll
        for(int mt=0;mt<4;mt++){
          MMA_BF16(acc[mt][nt], ah[mt][0],ah[mt][1],ah[mt][2],ah[mt][3], bh0,bh1);
          MMA_BF16(acc[mt][nt], al[mt][0],al[mt][1],al[mt][2],al[mt][3], bh0,bh1);
          MMA_BF16(acc[mt][nt], ah[mt][0],ah[mt][1],ah[mt][2],ah[mt][3], bl0,bl1);
        }
      }
    }
  }

  // ---- epilogue ----
  if(epi==0){
    #pragma unroll
    for(int mt=0;mt<4;mt++){
      int r = wm*64 + mt*16 + g;
      int row = m0 + r;
      bool p0 = (seq[row]==0), p1 = (seq[row+8]==0);
      float s0=0.f, s1=0.f;
      #pragma unroll
      for(int nt=0;nt<4;nt++){
        int col = n0 + wn*32 + nt*8 + 2*t;
        float b0v = bias[col], b1v = bias[col+1];
        float* cc = acc[mt][nt];
        float v00 = p0 ? 0.f : cc[0]+b0v;
        float v01 = p0 ? 0.f : cc[1]+b1v;
        float v10 = p1 ? 0.f : cc[2]+b0v;
        float v11 = p1 ? 0.f : cc[3]+b1v;
        float w0 = swv[col], w1 = swv[col+1];
        s0 += v00*w0 + v01*w1;
        s1 += v10*w0 + v11*w1;
        // split to hi/lo and store pair (2 halves each plane)
        float h0 = __bfloat162float(__float2bfloat16_rn(v00));
        float h1 = __bfloat162float(__float2bfloat16_rn(v01));
        *(uint32_t*)(Ch + (size_t)row*DD + col) = bfp2(h0,h1);
        *(uint32_t*)(Cl + (size_t)row*DD + col) = bfp2(v00-h0, v01-h1);
        float h2 = __bfloat162float(__float2bfloat16_rn(v10));
        float h3 = __bfloat162float(__float2bfloat16_rn(v11));
        *(uint32_t*)(Ch + (size_t)(row+8)*DD + col) = bfp2(h2,h3);
        *(uint32_t*)(Cl + (size_t)(row+8)*DD + col) = bfp2(v10-h2, v11-h3);
      }
      s0 += __shfl_xor_sync(0xffffffffu, s0, 1);
      s0 += __shfl_xor_sync(0xffffffffu, s0, 2);
      s1 += __shfl_xor_sync(0xffffffffu, s1, 1);
      s1 += __shfl_xor_sync(0xffffffffu, s1, 2);
      if(t==0){
        t_s[wn*128 + r]     = s0;
        t_s[wn*128 + r + 8] = s1;
      }
    }
    __syncthreads();
    if(tid < 128){
      float v = t_s[tid] + t_s[128+tid] + t_s[256+tid] + t_s[384+tid];
      g_tp[blockIdx.y*MM + m0 + tid] = v;
    }
  } else {
    #pragma unroll
    for(int mt=0;mt<4;mt++){
      int row = m0 + wm*64 + mt*16 + g;
      #pragma unroll
      for(int nt=0;nt<4;nt++){
        int col = n0 + wn*32 + nt*8 + 2*t;
        float b0v = bias[col], b1v = bias[col+1];
        float* cc = acc[mt][nt];
        size_t o0off = (size_t)row*DD + col;
        size_t o1off = (size_t)(row+8)*DD + col;
        float2 zh0 = unpk(*(const uint32_t*)(Ah + o0off));
        float2 zl0 = unpk(*(const uint32_t*)(Al + o0off));
        float2 zh1 = unpk(*(const uint32_t*)(Ah + o1off));
        float2 zl1 = unpk(*(const uint32_t*)(Al + o1off));
        float2 o0 = make_float2((zh0.x+zl0.x) + fmaxf(cc[0]+b0v,0.f),
                                (zh0.y+zl0.y) + fmaxf(cc[1]+b1v,0.f));
        float2 o1 = make_float2((zh1.x+zl1.x) + fmaxf(cc[2]+b0v,0.f),
                                (zh1.y+zl1.y) + fmaxf(cc[3]+b1v,0.f));
        *(float2*)&Cf[o0off] = o0;
        *(float2*)&Cf[o1off] = o1;
      }
    }
  }
}

// ---------------- K4: collapsed softmax (score_b cancels) ------------------
__global__ void k_weights(){
  int m = blockIdx.x*256 + threadIdx.x;
  int b = m >> 11, l = m & (LL-1);
  int len = g_len[b];
  float4 w = make_float4(0.f,0.f,0.f,0.f);
  if(l < len){
    const float* t0p = &g_tp[b*LL];
    const float* t1p = &g_tp[MM + b*LL];
    float t0 = t0p[l] + t1p[l];
    float sc[3], invc[3];
    #pragma unroll
    for(int si=0;si<3;si++){
      int s = si+2;
      int a = (l/s)*s;
      int e = min(a+s, len);
      float sum=0.f;
      for(int p=a;p<e;p++) sum += t0p[p] + t1p[p];
      float c = (float)(e-a);
      sc[si] = sum / c;
      invc[si] = 1.f/c;
    }
    float mx = fmaxf(fmaxf(t0,sc[0]),fmaxf(sc[1],sc[2]));
    float e0=expf(t0-mx), e2=expf(sc[0]-mx), e3=expf(sc[1]-mx), e4=expf(sc[2]-mx);
    float inv = 1.f/(e0 + 2.f*e2 + 3.f*e3 + 4.f*e4);
    w = make_float4(e0*inv, 2.f*e2*inv*invc[0], 3.f*e3*inv*invc[1], 4.f*e4*inv*invc[2]);
  }
  *(float4*)&g_w[m*4] = w;
}

// ---------------- K5: mix; 12 rows (lcm 2,3,4) per thread ------------------
__global__ __launch_bounds__(256) void k_mix(){
  int idx = blockIdx.x*256 + threadIdx.x;
  int cid = idx >> 6;                  // b*NCH + c
  int d4  = (idx & 63) << 2;
  int b = cid / NCH, c = cid - b*NCH;
  int l0 = c*12;
  size_t base = ((size_t)b*LL)*DD + d4;
  float s2[6][4], s3[4][4], s4[3][4];
  #pragma unroll
  for(int j=0;j<6;j++) s2[j][0]=s2[j][1]=s2[j][2]=s2[j][3]=0.f;
  #pragma unroll
  for(int j=0;j<4;j++) s3[j][0]=s3[j][1]=s3[j][2]=s3[j][3]=0.f;
  #pragma unroll
  for(int j=0;j<3;j++) s4[j][0]=s4[j][1]=s4[j][2]=s4[j][3]=0.f;
  // pass 1: accumulate group sums (rows >= len are zero in y -> no masking)
  #pragma unroll
  for(int j=0;j<12;j++){
    int l = l0 + j;
    if(l < LL){
      float v[4]; load4(g_yh, g_yl, base + (size_t)l*DD, v);
      #pragma unroll
      for(int i=0;i<4;i++){
        s2[j>>1][i] += v[i];
        s3[j/3][i]  += v[i];
        s4[j>>2][i] += v[i];
      }
    }
  }
  // pass 2: outputs (re-load y; L1-resident)
  #pragma unroll
  for(int j=0;j<12;j++){
    int l = l0 + j;
    if(l < LL){
      size_t off = base + (size_t)l*DD;
      float v[4]; load4(g_yh, g_yl, off, v);
      float4 w = *(const float4*)&g_w[((size_t)b*LL + l)*4];
      float o[4];
      #pragma unroll
      for(int i=0;i<4;i++)
        o[i] = w.x*v[i] + w.y*s2[j>>1][i] + w.z*s3[j/3][i] + w.w*s4[j>>2][i];
      uint2 H,L; split4(o,H,L);
      *(uint2*)(g_zh+off) = H;
      *(uint2*)(g_zl+off) = L;
    }
  }
}

// ---------------- launch ----------------------------------------------------
extern "C" void kernel_launch(void* const* d_in, const int* in_sizes, int n_in,
                              void* d_out, int out_size){
  const int*   seq = (const int*)  d_in[0];
  const float* emb = (const float*)d_in[2];
  const float* cw  = (const float*)d_in[3];
  const float* cb  = (const float*)d_in[4];
  const float* pw  = (const float*)d_in[5];
  const float* pb  = (const float*)d_in[6];
  const float* sw  = (const float*)d_in[7];
  const float* fw  = (const float*)d_in[9];
  const float* fb  = (const float*)d_in[10];
  float* out = (float*)d_out;

  __nv_bfloat16 *xch,*xcl,*yh,*yl,*zh,*zl;
  cudaGetSymbolAddress((void**)&xch, g_xch);
  cudaGetSymbolAddress((void**)&xcl, g_xcl);
  cudaGetSymbolAddress((void**)&yh,  g_yh);
  cudaGetSymbolAddress((void**)&yl,  g_yl);
  cudaGetSymbolAddress((void**)&zh,  g_zh);
  cudaGetSymbolAddress((void**)&zl,  g_zl);

  cudaFuncSetAttribute(k_tgemm, cudaFuncAttributeMaxDynamicSharedMemorySize, SMEM_BYTES);

  k_len    <<<BB, 256>>>(seq);
  k_buildxc<<<MM*64/(4*256), 256>>>(seq, emb, cw, cb);
  k_tgemm  <<<dim3(MM/128, 2), 256, SMEM_BYTES>>>(xch, xcl, pw, pb, seq, yh, yl, nullptr, sw, 0);
  k_weights<<<MM/256, 256>>>();
  k_mix    <<<BB*NCH*64/256, 256>>>();
  k_tgemm  <<<dim3(MM/128, 2), 256, SMEM_BYTES>>>(zh, zl, fw, fb, seq, nullptr, nullptr, out, sw, 1);
}

// round 8
// speedup vs baseline: 1.9081x; 1.0234x over previous
#include <cuda_runtime.h>
#include <cuda_bf16.h>
#include <cstdint>

#define BB 8
#define LL 2048
#define DD 256
#define MM (BB*LL)
#define NCH 171   // ceil(LL/12)

// ---------------- scratch (device globals; no runtime allocation) ----------
__device__ __nv_bfloat16 g_xch[MM*DD], g_xcl[MM*DD];  // conv out, hi/lo planes
__device__ __nv_bfloat16 g_yh [MM*DD], g_yl [MM*DD];  // proj out (masked)
__device__ __nv_bfloat16 g_zh [MM*DD], g_zl [MM*DD];  // weighted mix
__device__ __nv_bfloat16 g_pwh[DD*DD], g_pwl[DD*DD];  // proj W hi/lo
__device__ __nv_bfloat16 g_fwh[DD*DD], g_fwl[DD*DD];  // ff W hi/lo
__device__ float g_tp[2*MM];    // per-row partial score dots (2 N-halves)
__device__ float g_w [MM*4];    // softmax-combined weights

// ---------------- helpers ---------------------------------------------------
static __device__ __forceinline__ uint32_t su32(const void* p){
  uint32_t a;
  asm("{ .reg .u64 t; cvta.to.shared.u64 t, %1; cvt.u32.u64 %0, t; }" : "=r"(a) : "l"(p));
  return a;
}
static __device__ __forceinline__ uint32_t bfp2(float x0, float x1){
  uint32_t b0 = (uint32_t)__bfloat16_as_ushort(__float2bfloat16_rn(x0));
  uint32_t b1 = (uint32_t)__bfloat16_as_ushort(__float2bfloat16_rn(x1));
  return b0 | (b1<<16);
}
static __device__ __forceinline__ float2 unpk(uint32_t u){
  __nv_bfloat162 h = *reinterpret_cast<__nv_bfloat162*>(&u);
  return __bfloat1622float2(h);
}
static __device__ __forceinline__ void split4(const float* v, uint2& H, uint2& L){
  float h0 = __bfloat162float(__float2bfloat16_rn(v[0]));
  float h1 = __bfloat162float(__float2bfloat16_rn(v[1]));
  float h2 = __bfloat162float(__float2bfloat16_rn(v[2]));
  float h3 = __bfloat162float(__float2bfloat16_rn(v[3]));
  H = make_uint2(bfp2(h0,h1), bfp2(h2,h3));
  L = make_uint2(bfp2(v[0]-h0, v[1]-h1), bfp2(v[2]-h2, v[3]-h3));
}
static __device__ __forceinline__ void load4(const __nv_bfloat16* hi,
    const __nv_bfloat16* lo, size_t off, float* v){
  uint2 H = *(const uint2*)(hi+off);
  uint2 L = *(const uint2*)(lo+off);
  float2 a0=unpk(H.x), a1=unpk(H.y), b0=unpk(L.x), b1=unpk(L.y);
  v[0]=a0.x+b0.x; v[1]=a0.y+b0.y; v[2]=a1.x+b1.x; v[3]=a1.y+b1.y;
}
#define CP16(dst,src) asm volatile("cp.async.ca.shared.global [%0], [%1], 16;" :: "r"(dst), "l"(src))
#define CP_COMMIT()   asm volatile("cp.async.commit_group;" ::: "memory")
#define CP_WAIT0()    asm volatile("cp.async.wait_group 0;" ::: "memory")

// ---------------- K_wsplit: split proj & ff weights into hi/lo planes ------
__global__ void k_wsplit(const float* __restrict__ pw, const float* __restrict__ fw){
  int i = blockIdx.x*256 + threadIdx.x;           // 32768 threads, 4 floats each
  int which = i >= (DD*DD/4);
  int j = which ? i - DD*DD/4 : i;
  const float* src = which ? fw : pw;
  float4 v = *(const float4*)&src[j*4];
  float f[4] = {v.x,v.y,v.z,v.w};
  uint2 H,L; split4(f,H,L);
  __nv_bfloat16* dh = which ? g_fwh : g_pwh;
  __nv_bfloat16* dl = which ? g_fwl : g_pwl;
  *(uint2*)(dh + j*4) = H;
  *(uint2*)(dl + j*4) = L;
}

// ---------------- K1: embed(*16) + depthwise conv(4); 4 rows/thread --------
__global__ void k_buildxc(const int* __restrict__ seq,
                          const float* __restrict__ emb,
                          const float* __restrict__ cw,
                          const float* __restrict__ cb){
  int idx = blockIdx.x*256 + threadIdx.x;
  int cid = idx >> 6;
  int d4  = (idx & 63) << 2;
  int m0r = cid << 2;
  int l   = m0r & (LL-1);
  float e[7][4];
  #pragma unroll
  for(int k=0;k<7;k++){
    if(l + k < LL){
      int tok = seq[m0r + k];
      float4 t = *(const float4*)&emb[tok*DD + d4];
      e[k][0]=t.x*16.f; e[k][1]=t.y*16.f; e[k][2]=t.z*16.f; e[k][3]=t.w*16.f;
    } else {
      e[k][0]=e[k][1]=e[k][2]=e[k][3]=0.f;
    }
  }
  float4 cwv[4]; float cbv[4];
  #pragma unroll
  for(int i=0;i<4;i++){ cwv[i] = *(const float4*)&cw[(d4+i)*4]; cbv[i]=cb[d4+i]; }
  #pragma unroll
  for(int j=0;j<4;j++){
    float o[4];
    #pragma unroll
    for(int i=0;i<4;i++)
      o[i] = cbv[i] + cwv[i].x*e[j][i] + cwv[i].y*e[j+1][i]
                    + cwv[i].z*e[j+2][i] + cwv[i].w*e[j+3][i];
    uint2 H,L; split4(o,H,L);
    size_t off = (size_t)(m0r+j)*DD + d4;
    *(uint2*)(g_xch+off) = H;
    *(uint2*)(g_xcl+off) = L;
  }
}

// ============== warp-MMA GEMM: all operands pre-split hi/lo bf16 ===========
// 3-term: Ahi*Whi + Alo*Whi + Ahi*Wlo, fp32 accum.
// epi=0 (proj): y(hi/lo) = pad?0:acc+bias; per-row partial dot -> g_tp
// epi=1 (ff):   Cf = (zh+zl) + relu(acc+bias)
#define PK 72
#define PKW 36
#define TILE_HALFS (128*PK)
#define SMEM_BYTES (4*TILE_HALFS*2 + 2048)

#define MMA_BF16(c, A0,A1,A2,A3, B0,B1) \
  asm volatile("mma.sync.aligned.m16n8k16.row.col.f32.bf16.bf16.f32 " \
    "{%0,%1,%2,%3}, {%4,%5,%6,%7}, {%8,%9}, {%0,%1,%2,%3};" \
    : "+f"((c)[0]), "+f"((c)[1]), "+f"((c)[2]), "+f"((c)[3]) \
    : "r"(A0), "r"(A1), "r"(A2), "r"(A3), "r"(B0), "r"(B1))

__global__ __launch_bounds__(256,2) void k_tgemm(
    const __nv_bfloat16* __restrict__ Ah, const __nv_bfloat16* __restrict__ Al,
    const __nv_bfloat16* __restrict__ Wh, const __nv_bfloat16* __restrict__ Wl,
    const float* __restrict__ bias, const int* __restrict__ seq,
    __nv_bfloat16* __restrict__ Ch, __nv_bfloat16* __restrict__ Cl,
    float* __restrict__ Cf, const float* __restrict__ swv, int epi)
{
  extern __shared__ __align__(16) char smraw[];
  float* t_s = (float*)(smraw + 4*TILE_HALFS*2);
  const uint32_t sbase = su32(smraw);
  const uint32_t* wAh = (const uint32_t*)smraw;
  const uint32_t* wAl = wAh + TILE_HALFS/2;
  const uint32_t* wWh = wAl + TILE_HALFS/2;
  const uint32_t* wWl = wWh + TILE_HALFS/2;

  const int tid = threadIdx.x;
  const int wid = tid>>5, lane = tid&31;
  const int g = lane>>2, t = lane&3;
  const int wm = wid & 1, wn = wid >> 1;
  const int m0 = blockIdx.x*128, n0 = blockIdx.y*128;

  const __nv_bfloat16* gsrc[4] = {Ah, Al, Wh, Wl};

  float acc[4][4][4];
  #pragma unroll
  for(int i=0;i<4;i++)
    #pragma unroll
    for(int j=0;j<4;j++)
      #pragma unroll
      for(int q=0;q<4;q++) acc[i][j][q]=0.f;

  for(int c4=0;c4<4;c4++){
    const int k0 = c4*64;
    if(c4) __syncthreads();
    // 4 planes x 128 rows x 64 halves, pure 16B async copies
    #pragma unroll
    for(int u=tid; u<4096; u+=256){
      int plane = u>>10;
      int v = u & 1023;
      int r = v>>3, q = v&7;
      int row0 = (plane<2) ? m0 : n0;
      const __nv_bfloat16* src = gsrc[plane] + (size_t)(row0+r)*DD + k0 + q*8;
      uint32_t dst = sbase + (plane*TILE_HALFS + r*PK + q*8)*2;
      CP16(dst, src);
    }
    CP_COMMIT(); CP_WAIT0();
    __syncthreads();
    #pragma unroll
    for(int ks=0; ks<4; ks++){
      const int kw = ks*8;
      uint32_t ah[4][4], al[4][4];
      #pragma unroll
      for(int mt=0;mt<4;mt++){
        int r0 = wm*64 + mt*16 + g;
        int b0i = r0*PKW + kw + t;
        int b8i = (r0+8)*PKW + kw + t;
        ah[mt][0]=wAh[b0i];   ah[mt][1]=wAh[b8i];
        ah[mt][2]=wAh[b0i+4]; ah[mt][3]=wAh[b8i+4];
        al[mt][0]=wAl[b0i];   al[mt][1]=wAl[b8i];
        al[mt][2]=wAl[b0i+4]; al[mt][3]=wAl[b8i+4];
      }
      #pragma unroll
      for(int nt=0;nt<4;nt++){
        int nr = wn*32 + nt*8 + g;
        int bi = nr*PKW + kw + t;
        uint32_t bh0=wWh[bi], bh1=wWh[bi+4];
        uint32_t bl0=wWl[bi], bl1=wWl[bi+4];
        #pragma unroll
        for(int mt=0;mt<4;mt++){
          MMA_BF16(acc[mt][nt], ah[mt][0],ah[mt][1],ah[mt][2],ah[mt][3], bh0,bh1);
          MMA_BF16(acc[mt][nt], al[mt][0],al[mt][1],al[mt][2],al[mt][3], bh0,bh1);
          MMA_BF16(acc[mt][nt], ah[mt][0],ah[mt][1],ah[mt][2],ah[mt][3], bl0,bl1);
        }
      }
    }
  }

  // ---- epilogue ----
  if(epi==0){
    #pragma unroll
    for(int mt=0;mt<4;mt++){
      int r = wm*64 + mt*16 + g;
      int row = m0 + r;
      bool p0 = (seq[row]==0), p1 = (seq[row+8]==0);
      float s0=0.f, s1=0.f;
      #pragma unroll
      for(int nt=0;nt<4;nt++){
        int col = n0 + wn*32 + nt*8 + 2*t;
        float b0v = bias[col], b1v = bias[col+1];
        float* cc = acc[mt][nt];
        float v00 = p0 ? 0.f : cc[0]+b0v;
        float v01 = p0 ? 0.f : cc[1]+b1v;
        float v10 = p1 ? 0.f : cc[2]+b0v;
        float v11 = p1 ? 0.f : cc[3]+b1v;
        float w0 = swv[col], w1 = swv[col+1];
        s0 += v00*w0 + v01*w1;
        s1 += v10*w0 + v11*w1;
        float h0 = __bfloat162float(__float2bfloat16_rn(v00));
        float h1 = __bfloat162float(__float2bfloat16_rn(v01));
        *(uint32_t*)(Ch + (size_t)row*DD + col) = bfp2(h0,h1);
        *(uint32_t*)(Cl + (size_t)row*DD + col) = bfp2(v00-h0, v01-h1);
        float h2 = __bfloat162float(__float2bfloat16_rn(v10));
        float h3 = __bfloat162float(__float2bfloat16_rn(v11));
        *(uint32_t*)(Ch + (size_t)(row+8)*DD + col) = bfp2(h2,h3);
        *(uint32_t*)(Cl + (size_t)(row+8)*DD + col) = bfp2(v10-h2, v11-h3);
      }
      s0 += __shfl_xor_sync(0xffffffffu, s0, 1);
      s0 += __shfl_xor_sync(0xffffffffu, s0, 2);
      s1 += __shfl_xor_sync(0xffffffffu, s1, 1);
      s1 += __shfl_xor_sync(0xffffffffu, s1, 2);
      if(t==0){
        t_s[wn*128 + r]     = s0;
        t_s[wn*128 + r + 8] = s1;
      }
    }
    __syncthreads();
    if(tid < 128){
      float v = t_s[tid] + t_s[128+tid] + t_s[256+tid] + t_s[384+tid];
      g_tp[blockIdx.y*MM + m0 + tid] = v;
    }
  } else {
    #pragma unroll
    for(int mt=0;mt<4;mt++){
      int row = m0 + wm*64 + mt*16 + g;
      #pragma unroll
      for(int nt=0;nt<4;nt++){
        int col = n0 + wn*32 + nt*8 + 2*t;
        float b0v = bias[col], b1v = bias[col+1];
        float* cc = acc[mt][nt];
        size_t o0off = (size_t)row*DD + col;
        size_t o1off = (size_t)(row+8)*DD + col;
        float2 zh0 = unpk(*(const uint32_t*)(Ah + o0off));
        float2 zl0 = unpk(*(const uint32_t*)(Al + o0off));
        float2 zh1 = unpk(*(const uint32_t*)(Ah + o1off));
        float2 zl1 = unpk(*(const uint32_t*)(Al + o1off));
        float2 o0 = make_float2((zh0.x+zl0.x) + fmaxf(cc[0]+b0v,0.f),
                                (zh0.y+zl0.y) + fmaxf(cc[1]+b1v,0.f));
        float2 o1 = make_float2((zh1.x+zl1.x) + fmaxf(cc[2]+b0v,0.f),
                                (zh1.y+zl1.y) + fmaxf(cc[3]+b1v,0.f));
        *(float2*)&Cf[o0off] = o0;
        *(float2*)&Cf[o1off] = o1;
      }
    }
  }
}

// ---------------- K4: fused len + smem-tiled collapsed softmax -------------
__global__ void k_weights(const int* __restrict__ seq){
  __shared__ float ts[262];
  __shared__ int s_len;
  int b  = blockIdx.x >> 3;
  int l0 = (blockIdx.x & 7) * 256;
  int tid = threadIdx.x;
  // length of this batch (count of nonzero)
  if(tid==0) s_len = 0;
  __syncthreads();
  {
    int c=0;
    const int* sb = &seq[b*LL];
    #pragma unroll
    for(int i=0;i<8;i++) c += (sb[tid + i*256] != 0);
    #pragma unroll
    for(int o=16;o>0;o>>=1) c += __shfl_xor_sync(0xffffffffu,c,o);
    if((tid&31)==0) atomicAdd(&s_len, c);
  }
  // t window [l0-3, l0+258]
  const float* t0p = &g_tp[b*LL];
  const float* t1p = &g_tp[MM + b*LL];
  for(int i=tid; i<262; i+=256){
    int p = l0 - 3 + i;
    ts[i] = (p>=0 && p<LL) ? (t0p[p] + t1p[p]) : 0.f;
  }
  __syncthreads();
  int len = s_len;
  int l = l0 + tid;
  float4 w = make_float4(0.f,0.f,0.f,0.f);
  if(l < len){
    float t0 = ts[tid+3];
    float sc[3], invc[3];
    #pragma unroll
    for(int si=0;si<3;si++){
      int s = si+2;
      int a = (l/s)*s;
      int e = min(a+s, len);
      float sum=0.f;
      for(int p=a;p<e;p++) sum += ts[p - l0 + 3];
      float c = (float)(e-a);
      sc[si] = sum / c;
      invc[si] = 1.f/c;
    }
    float mx = fmaxf(fmaxf(t0,sc[0]),fmaxf(sc[1],sc[2]));
    float e0=expf(t0-mx), e2=expf(sc[0]-mx), e3=expf(sc[1]-mx), e4=expf(sc[2]-mx);
    float inv = 1.f/(e0 + 2.f*e2 + 3.f*e3 + 4.f*e4);
    w = make_float4(e0*inv, 2.f*e2*inv*invc[0], 3.f*e3*inv*invc[1], 4.f*e4*inv*invc[2]);
  }
  *(float4*)&g_w[((size_t)b*LL + l)*4] = w;
}

// ---------------- K5: mix; 12 rows/thread, single pass (rows in regs) ------
__global__ __launch_bounds__(256) void k_mix(){
  int idx = blockIdx.x*256 + threadIdx.x;
  int cid = idx >> 6;
  int d4  = (idx & 63) << 2;
  int b = cid / NCH, c = cid - b*NCH;
  int l0 = c*12;
  size_t base = ((size_t)b*LL)*DD + d4;
  float v[12][4];
  float s2[6][4], s3[4][4];
  #pragma unroll
  for(int j=0;j<6;j++) s2[j][0]=s2[j][1]=s2[j][2]=s2[j][3]=0.f;
  #pragma unroll
  for(int j=0;j<4;j++) s3[j][0]=s3[j][1]=s3[j][2]=s3[j][3]=0.f;
  #pragma unroll
  for(int j=0;j<12;j++){
    int l = l0 + j;
    if(l < LL){
      load4(g_yh, g_yl, base + (size_t)l*DD, v[j]);
      #pragma unroll
      for(int i=0;i<4;i++){
        s2[j>>1][i] += v[j][i];
        s3[j/3][i]  += v[j][i];
      }
    } else {
      v[j][0]=v[j][1]=v[j][2]=v[j][3]=0.f;
    }
  }
  #pragma unroll
  for(int j=0;j<12;j++){
    int l = l0 + j;
    if(l < LL){
      size_t off = base + (size_t)l*DD;
      float4 w = *(const float4*)&g_w[((size_t)b*LL + l)*4];
      int q = j>>2;
      float o[4];
      #pragma unroll
      for(int i=0;i<4;i++)
        o[i] = w.x*v[j][i] + w.y*s2[j>>1][i] + w.z*s3[j/3][i]
             + w.w*(s2[2*q][i] + s2[2*q+1][i]);
      uint2 H,L; split4(o,H,L);
      *(uint2*)(g_zh+off) = H;
      *(uint2*)(g_zl+off) = L;
    }
  }
}

// ---------------- launch ----------------------------------------------------
extern "C" void kernel_launch(void* const* d_in, const int* in_sizes, int n_in,
                              void* d_out, int out_size){
  const int*   seq = (const int*)  d_in[0];
  const float* emb = (const float*)d_in[2];
  const float* cw  = (const float*)d_in[3];
  const float* cb  = (const float*)d_in[4];
  const float* pw  = (const float*)d_in[5];
  const float* pb  = (const float*)d_in[6];
  const float* sw  = (const float*)d_in[7];
  const float* fw  = (const float*)d_in[9];
  const float* fb  = (const float*)d_in[10];
  float* out = (float*)d_out;

  __nv_bfloat16 *xch,*xcl,*yh,*yl,*zh,*zl,*pwh,*pwl,*fwh,*fwl;
  cudaGetSymbolAddress((void**)&xch, g_xch);
  cudaGetSymbolAddress((void**)&xcl, g_xcl);
  cudaGetSymbolAddress((void**)&yh,  g_yh);
  cudaGetSymbolAddress((void**)&yl,  g_yl);
  cudaGetSymbolAddress((void**)&zh,  g_zh);
  cudaGetSymbolAddress((void**)&zl,  g_zl);
  cudaGetSymbolAddress((void**)&pwh, g_pwh);
  cudaGetSymbolAddress((void**)&pwl, g_pwl);
  cudaGetSymbolAddress((void**)&fwh, g_fwh);
  cudaGetSymbolAddress((void**)&fwl, g_fwl);

  cudaFuncSetAttribute(k_tgemm, cudaFuncAttributeMaxDynamicSharedMemorySize, SMEM_BYTES);

  k_wsplit <<<2*DD*DD/4/256, 256>>>(pw, fw);
  k_buildxc<<<MM*64/(4*256), 256>>>(seq, emb, cw, cb);
  k_tgemm  <<<dim3(MM/128, 2), 256, SMEM_BYTES>>>(xch, xcl, pwh, pwl, pb, seq, yh, yl, nullptr, sw, 0);
  k_weights<<<MM/256, 256>>>(seq);
  k_mix    <<<BB*NCH*64/256, 256>>>();
  k_tgemm  <<<dim3(MM/128, 2), 256, SMEM_BYTES>>>(zh, zl, fwh, fwl, fb, seq, nullptr, nullptr, out, sw, 1);
}

// round 9
// speedup vs baseline: 2.0217x; 1.0595x over previous
#include <cuda_runtime.h>
#include <cuda_bf16.h>
#include <cstdint>

#define BB 8
#define LL 2048
#define DD 256
#define MM (BB*LL)
#define NCH 171   // ceil(LL/12)

// ---------------- scratch (device globals; no runtime allocation) ----------
__device__ __nv_bfloat16 g_xch[MM*DD], g_xcl[MM*DD];  // conv out, hi/lo planes
__device__ __nv_bfloat16 g_yh [MM*DD], g_yl [MM*DD];  // proj out (masked)
__device__ __nv_bfloat16 g_zh [MM*DD], g_zl [MM*DD];  // weighted mix
__device__ __nv_bfloat16 g_pwh[DD*DD], g_pwl[DD*DD];  // proj W hi/lo
__device__ __nv_bfloat16 g_fwh[DD*DD], g_fwl[DD*DD];  // ff W hi/lo
__device__ float g_tp[2*MM];    // per-row partial score dots (2 N-halves)
__device__ int   g_len[BB];

// ---------------- helpers ---------------------------------------------------
static __device__ __forceinline__ uint32_t su32(const void* p){
  uint32_t a;
  asm("{ .reg .u64 t; cvta.to.shared.u64 t, %1; cvt.u32.u64 %0, t; }" : "=r"(a) : "l"(p));
  return a;
}
static __device__ __forceinline__ uint32_t bfp2(float x0, float x1){
  uint32_t b0 = (uint32_t)__bfloat16_as_ushort(__float2bfloat16_rn(x0));
  uint32_t b1 = (uint32_t)__bfloat16_as_ushort(__float2bfloat16_rn(x1));
  return b0 | (b1<<16);
}
static __device__ __forceinline__ float2 unpk(uint32_t u){
  __nv_bfloat162 h = *reinterpret_cast<__nv_bfloat162*>(&u);
  return __bfloat1622float2(h);
}
static __device__ __forceinline__ void split4(const float* v, uint2& H, uint2& L){
  float h0 = __bfloat162float(__float2bfloat16_rn(v[0]));
  float h1 = __bfloat162float(__float2bfloat16_rn(v[1]));
  float h2 = __bfloat162float(__float2bfloat16_rn(v[2]));
  float h3 = __bfloat162float(__float2bfloat16_rn(v[3]));
  H = make_uint2(bfp2(h0,h1), bfp2(h2,h3));
  L = make_uint2(bfp2(v[0]-h0, v[1]-h1), bfp2(v[2]-h2, v[3]-h3));
}
static __device__ __forceinline__ void load4(const __nv_bfloat16* hi,
    const __nv_bfloat16* lo, size_t off, float* v){
  uint2 H = *(const uint2*)(hi+off);
  uint2 L = *(const uint2*)(lo+off);
  float2 a0=unpk(H.x), a1=unpk(H.y), b0=unpk(L.x), b1=unpk(L.y);
  v[0]=a0.x+b0.x; v[1]=a0.y+b0.y; v[2]=a1.x+b1.x; v[3]=a1.y+b1.y;
}
#define CP16(dst,src) asm volatile("cp.async.ca.shared.global [%0], [%1], 16;" :: "r"(dst), "l"(src))
#define CP_COMMIT()   asm volatile("cp.async.commit_group;" ::: "memory")
#define CP_WAIT0()    asm volatile("cp.async.wait_group 0;" ::: "memory")

// ---------------- K_prep: len(8) + wsplit(128) + buildxc(1024) in one grid -
#define LEN_BLKS 8
#define WS_BLKS  128
#define BX_BLKS  1024
__global__ void k_prep(const int* __restrict__ seq, const float* __restrict__ emb,
                       const float* __restrict__ cw, const float* __restrict__ cb,
                       const float* __restrict__ pw, const float* __restrict__ fw){
  int bx = blockIdx.x;
  int tid = threadIdx.x;
  if(bx < LEN_BLKS){
    __shared__ int cnt;
    if(tid==0) cnt=0;
    __syncthreads();
    int c=0;
    const int* sb = &seq[bx*LL];
    #pragma unroll
    for(int i=0;i<8;i++) c += (sb[tid + i*256] != 0);
    #pragma unroll
    for(int o=16;o>0;o>>=1) c += __shfl_xor_sync(0xffffffffu,c,o);
    if((tid&31)==0) atomicAdd(&cnt,c);
    __syncthreads();
    if(tid==0) g_len[bx]=cnt;
    return;
  }
  if(bx < LEN_BLKS + WS_BLKS){
    int i = (bx-LEN_BLKS)*256 + tid;
    int which = i >= (DD*DD/4);
    int j = which ? i - DD*DD/4 : i;
    const float* src = which ? fw : pw;
    float4 v = *(const float4*)&src[j*4];
    float f[4] = {v.x,v.y,v.z,v.w};
    uint2 H,L; split4(f,H,L);
    __nv_bfloat16* dh = which ? g_fwh : g_pwh;
    __nv_bfloat16* dl = which ? g_fwl : g_pwl;
    *(uint2*)(dh + j*4) = H;
    *(uint2*)(dl + j*4) = L;
    return;
  }
  // buildxc: embed(*16) + depthwise conv(4); 4 rows/thread
  int idx = (bx - LEN_BLKS - WS_BLKS)*256 + tid;
  int cid = idx >> 6;
  int d4  = (idx & 63) << 2;
  int m0r = cid << 2;
  int l   = m0r & (LL-1);
  float e[7][4];
  #pragma unroll
  for(int k=0;k<7;k++){
    if(l + k < LL){
      int tok = seq[m0r + k];
      float4 t = *(const float4*)&emb[tok*DD + d4];
      e[k][0]=t.x*16.f; e[k][1]=t.y*16.f; e[k][2]=t.z*16.f; e[k][3]=t.w*16.f;
    } else {
      e[k][0]=e[k][1]=e[k][2]=e[k][3]=0.f;
    }
  }
  float4 cwv[4]; float cbv[4];
  #pragma unroll
  for(int i=0;i<4;i++){ cwv[i] = *(const float4*)&cw[(d4+i)*4]; cbv[i]=cb[d4+i]; }
  #pragma unroll
  for(int j=0;j<4;j++){
    float o[4];
    #pragma unroll
    for(int i=0;i<4;i++)
      o[i] = cbv[i] + cwv[i].x*e[j][i] + cwv[i].y*e[j+1][i]
                    + cwv[i].z*e[j+2][i] + cwv[i].w*e[j+3][i];
    uint2 H,L; split4(o,H,L);
    size_t off = (size_t)(m0r+j)*DD + d4;
    *(uint2*)(g_xch+off) = H;
    *(uint2*)(g_xcl+off) = L;
  }
}

// ============== warp-MMA GEMM: all operands pre-split hi/lo bf16 ===========
#define PK 72
#define PKW 36
#define TILE_HALFS (128*PK)
#define SMEM_BYTES (4*TILE_HALFS*2 + 2048)

#define MMA_BF16(c, A0,A1,A2,A3, B0,B1) \
  asm volatile("mma.sync.aligned.m16n8k16.row.col.f32.bf16.bf16.f32 " \
    "{%0,%1,%2,%3}, {%4,%5,%6,%7}, {%8,%9}, {%0,%1,%2,%3};" \
    : "+f"((c)[0]), "+f"((c)[1]), "+f"((c)[2]), "+f"((c)[3]) \
    : "r"(A0), "r"(A1), "r"(A2), "r"(A3), "r"(B0), "r"(B1))

__global__ __launch_bounds__(256,2) void k_tgemm(
    const __nv_bfloat16* __restrict__ Ah, const __nv_bfloat16* __restrict__ Al,
    const __nv_bfloat16* __restrict__ Wh, const __nv_bfloat16* __restrict__ Wl,
    const float* __restrict__ bias, const int* __restrict__ seq,
    __nv_bfloat16* __restrict__ Ch, __nv_bfloat16* __restrict__ Cl,
    float* __restrict__ Cf, const float* __restrict__ swv, int epi)
{
  extern __shared__ __align__(16) char smraw[];
  float* t_s = (float*)(smraw + 4*TILE_HALFS*2);
  const uint32_t sbase = su32(smraw);
  const uint32_t* wAh = (const uint32_t*)smraw;
  const uint32_t* wAl = wAh + TILE_HALFS/2;
  const uint32_t* wWh = wAl + TILE_HALFS/2;
  const uint32_t* wWl = wWh + TILE_HALFS/2;

  const int tid = threadIdx.x;
  const int wid = tid>>5, lane = tid&31;
  const int g = lane>>2, t = lane&3;
  const int wm = wid & 1, wn = wid >> 1;
  const int m0 = blockIdx.x*128, n0 = blockIdx.y*128;

  const __nv_bfloat16* gsrc[4] = {Ah, Al, Wh, Wl};

  float acc[4][4][4];
  #pragma unroll
  for(int i=0;i<4;i++)
    #pragma unroll
    for(int j=0;j<4;j++)
      #pragma unroll
      for(int q=0;q<4;q++) acc[i][j][q]=0.f;

  for(int c4=0;c4<4;c4++){
    const int k0 = c4*64;
    if(c4) __syncthreads();
    #pragma unroll
    for(int u=tid; u<4096; u+=256){
      int plane = u>>10;
      int v = u & 1023;
      int r = v>>3, q = v&7;
      int row0 = (plane<2) ? m0 : n0;
      const __nv_bfloat16* src = gsrc[plane] + (size_t)(row0+r)*DD + k0 + q*8;
      uint32_t dst = sbase + (plane*TILE_HALFS + r*PK + q*8)*2;
      CP16(dst, src);
    }
    CP_COMMIT(); CP_WAIT0();
    __syncthreads();
    #pragma unroll
    for(int ks=0; ks<4; ks++){
      const int kw = ks*8;
      uint32_t ah[4][4], al[4][4];
      #pragma unroll
      for(int mt=0;mt<4;mt++){
        int r0 = wm*64 + mt*16 + g;
        int b0i = r0*PKW + kw + t;
        int b8i = (r0+8)*PKW + kw + t;
        ah[mt][0]=wAh[b0i];   ah[mt][1]=wAh[b8i];
        ah[mt][2]=wAh[b0i+4]; ah[mt][3]=wAh[b8i+4];
        al[mt][0]=wAl[b0i];   al[mt][1]=wAl[b8i];
        al[mt][2]=wAl[b0i+4]; al[mt][3]=wAl[b8i+4];
      }
      #pragma unroll
      for(int nt=0;nt<4;nt++){
        int nr = wn*32 + nt*8 + g;
        int bi = nr*PKW + kw + t;
        uint32_t bh0=wWh[bi], bh1=wWh[bi+4];
        uint32_t bl0=wWl[bi], bl1=wWl[bi+4];
        #pragma unroll
        for(int mt=0;mt<4;mt++){
          MMA_BF16(acc[mt][nt], ah[mt][0],ah[mt][1],ah[mt][2],ah[mt][3], bh0,bh1);
          MMA_BF16(acc[mt][nt], al[mt][0],al[mt][1],al[mt][2],al[mt][3], bh0,bh1);
          MMA_BF16(acc[mt][nt], ah[mt][0],ah[mt][1],ah[mt][2],ah[mt][3], bl0,bl1);
        }
      }
    }
  }

  // ---- epilogue ----
  if(epi==0){
    #pragma unroll
    for(int mt=0;mt<4;mt++){
      int r = wm*64 + mt*16 + g;
      int row = m0 + r;
      bool p0 = (seq[row]==0), p1 = (seq[row+8]==0);
      float s0=0.f, s1=0.f;
      #pragma unroll
      for(int nt=0;nt<4;nt++){
        int col = n0 + wn*32 + nt*8 + 2*t;
        float b0v = bias[col], b1v = bias[col+1];
        float* cc = acc[mt][nt];
        float v00 = p0 ? 0.f : cc[0]+b0v;
        float v01 = p0 ? 0.f : cc[1]+b1v;
        float v10 = p1 ? 0.f : cc[2]+b0v;
        float v11 = p1 ? 0.f : cc[3]+b1v;
        float w0 = swv[col], w1 = swv[col+1];
        s0 += v00*w0 + v01*w1;
        s1 += v10*w0 + v11*w1;
        float h0 = __bfloat162float(__float2bfloat16_rn(v00));
        float h1 = __bfloat162float(__float2bfloat16_rn(v01));
        *(uint32_t*)(Ch + (size_t)row*DD + col) = bfp2(h0,h1);
        *(uint32_t*)(Cl + (size_t)row*DD + col) = bfp2(v00-h0, v01-h1);
        float h2 = __bfloat162float(__float2bfloat16_rn(v10));
        float h3 = __bfloat162float(__float2bfloat16_rn(v11));
        *(uint32_t*)(Ch + (size_t)(row+8)*DD + col) = bfp2(h2,h3);
        *(uint32_t*)(Cl + (size_t)(row+8)*DD + col) = bfp2(v10-h2, v11-h3);
      }
      s0 += __shfl_xor_sync(0xffffffffu, s0, 1);
      s0 += __shfl_xor_sync(0xffffffffu, s0, 2);
      s1 += __shfl_xor_sync(0xffffffffu, s1, 1);
      s1 += __shfl_xor_sync(0xffffffffu, s1, 2);
      if(t==0){
        t_s[wn*128 + r]     = s0;
        t_s[wn*128 + r + 8] = s1;
      }
    }
    __syncthreads();
    if(tid < 128){
      float v = t_s[tid] + t_s[128+tid] + t_s[256+tid] + t_s[384+tid];
      g_tp[blockIdx.y*MM + m0 + tid] = v;
    }
  } else {
    #pragma unroll
    for(int mt=0;mt<4;mt++){
      int row = m0 + wm*64 + mt*16 + g;
      #pragma unroll
      for(int nt=0;nt<4;nt++){
        int col = n0 + wn*32 + nt*8 + 2*t;
        float b0v = bias[col], b1v = bias[col+1];
        float* cc = acc[mt][nt];
        size_t o0off = (size_t)row*DD + col;
        size_t o1off = (size_t)(row+8)*DD + col;
        float2 zh0 = unpk(*(const uint32_t*)(Ah + o0off));
        float2 zl0 = unpk(*(const uint32_t*)(Al + o0off));
        float2 zh1 = unpk(*(const uint32_t*)(Ah + o1off));
        float2 zl1 = unpk(*(const uint32_t*)(Al + o1off));
        float2 o0 = make_float2((zh0.x+zl0.x) + fmaxf(cc[0]+b0v,0.f),
                                (zh0.y+zl0.y) + fmaxf(cc[1]+b1v,0.f));
        float2 o1 = make_float2((zh1.x+zl1.x) + fmaxf(cc[2]+b0v,0.f),
                                (zh1.y+zl1.y) + fmaxf(cc[3]+b1v,0.f));
        *(float2*)&Cf[o0off] = o0;
        *(float2*)&Cf[o1off] = o1;
      }
    }
  }
}

// ------- K_mixw: fused collapsed-softmax weights + mix, 12 rows/thread -----
// l0 = 12*c is a multiple of lcm(2,3,4): each chunk's 12 rows contain whole
// s=2/3/4 groups, so weights need only the chunk's own 12 t-values.
__global__ __launch_bounds__(256) void k_mixw(){
  __shared__ float4 wsm[48];            // weights for the block's 4 cids x 12 rows
  int tid = threadIdx.x;
  int cid0 = blockIdx.x*4;
  if(tid < 48){
    int s = tid;
    int cid = cid0 + s/12, j = s - (s/12)*12;
    int b = cid/NCH, c = cid - b*NCH;
    int l0 = c*12, l = l0 + j;
    int len = g_len[b];
    float4 w = make_float4(0.f,0.f,0.f,0.f);
    if(l < LL && l < len){
      const float* t0p = &g_tp[b*LL];
      const float* t1p = &g_tp[MM + b*LL];
      float tv[12];
      #pragma unroll
      for(int jj=0;jj<12;jj++){
        int p = l0 + jj;
        tv[jj] = (p < LL) ? (t0p[p] + t1p[p]) : 0.f;   // pad rows have t=0
      }
      int a2 = j & ~1, a3 = (j/3)*3, a4 = j & ~3;
      float s2v = tv[a2]+tv[a2+1];
      float s3v = tv[a3]+tv[a3+1]+tv[a3+2];
      float s4v = tv[a4]+tv[a4+1]+tv[a4+2]+tv[a4+3];
      float c2 = (float)(min(l0+a2+2, len) - (l0+a2));
      float c3 = (float)(min(l0+a3+3, len) - (l0+a3));
      float c4 = (float)(min(l0+a4+4, len) - (l0+a4));
      float m2 = s2v/c2, m3 = s3v/c3, m4 = s4v/c4;
      float t0 = tv[j];
      float mx = fmaxf(fmaxf(t0,m2), fmaxf(m3,m4));
      float e0=expf(t0-mx), e2=expf(m2-mx), e3=expf(m3-mx), e4=expf(m4-mx);
      float inv = 1.f/(e0 + 2.f*e2 + 3.f*e3 + 4.f*e4);
      w = make_float4(e0*inv, 2.f*e2*inv/c2, 3.f*e3*inv/c3, 4.f*e4*inv/c4);
    }
    wsm[s] = w;
  }
  __syncthreads();

  int idx = blockIdx.x*256 + tid;
  int cid = idx >> 6;
  int d4  = (idx & 63) << 2;
  int b = cid / NCH, c = cid - b*NCH;
  int l0 = c*12;
  int slot0 = (tid>>6)*12;
  size_t base = ((size_t)b*LL)*DD + d4;
  float v[12][4];
  float s2[6][4], s3[4][4];
  #pragma unroll
  for(int j=0;j<6;j++) s2[j][0]=s2[j][1]=s2[j][2]=s2[j][3]=0.f;
  #pragma unroll
  for(int j=0;j<4;j++) s3[j][0]=s3[j][1]=s3[j][2]=s3[j][3]=0.f;
  #pragma unroll
  for(int j=0;j<12;j++){
    int l = l0 + j;
    if(l < LL){
      load4(g_yh, g_yl, base + (size_t)l*DD, v[j]);
      #pragma unroll
      for(int i=0;i<4;i++){
        s2[j>>1][i] += v[j][i];
        s3[j/3][i]  += v[j][i];
      }
    } else {
      v[j][0]=v[j][1]=v[j][2]=v[j][3]=0.f;
    }
  }
  #pragma unroll
  for(int j=0;j<12;j++){
    int l = l0 + j;
    if(l < LL){
      size_t off = base + (size_t)l*DD;
      float4 w = wsm[slot0 + j];
      int q = j>>2;
      float o[4];
      #pragma unroll
      for(int i=0;i<4;i++)
        o[i] = w.x*v[j][i] + w.y*s2[j>>1][i] + w.z*s3[j/3][i]
             + w.w*(s2[2*q][i] + s2[2*q+1][i]);
      uint2 H,L; split4(o,H,L);
      *(uint2*)(g_zh+off) = H;
      *(uint2*)(g_zl+off) = L;
    }
  }
}

// ---------------- launch ----------------------------------------------------
extern "C" void kernel_launch(void* const* d_in, const int* in_sizes, int n_in,
                              void* d_out, int out_size){
  const int*   seq = (const int*)  d_in[0];
  const float* emb = (const float*)d_in[2];
  const float* cw  = (const float*)d_in[3];
  const float* cb  = (const float*)d_in[4];
  const float* pw  = (const float*)d_in[5];
  const float* pb  = (const float*)d_in[6];
  const float* sw  = (const float*)d_in[7];
  const float* fw  = (const float*)d_in[9];
  const float* fb  = (const float*)d_in[10];
  float* out = (float*)d_out;

  __nv_bfloat16 *xch,*xcl,*yh,*yl,*zh,*zl,*pwh,*pwl,*fwh,*fwl;
  cudaGetSymbolAddress((void**)&xch, g_xch);
  cudaGetSymbolAddress((void**)&xcl, g_xcl);
  cudaGetSymbolAddress((void**)&yh,  g_yh);
  cudaGetSymbolAddress((void**)&yl,  g_yl);
  cudaGetSymbolAddress((void**)&zh,  g_zh);
  cudaGetSymbolAddress((void**)&zl,  g_zl);
  cudaGetSymbolAddress((void**)&pwh, g_pwh);
  cudaGetSymbolAddress((void**)&pwl, g_pwl);
  cudaGetSymbolAddress((void**)&fwh, g_fwh);
  cudaGetSymbolAddress((void**)&fwl, g_fwl);

  cudaFuncSetAttribute(k_tgemm, cudaFuncAttributeMaxDynamicSharedMemorySize, SMEM_BYTES);

  k_prep <<<LEN_BLKS+WS_BLKS+BX_BLKS, 256>>>(seq, emb, cw, cb, pw, fw);
  k_tgemm<<<dim3(MM/128, 2), 256, SMEM_BYTES>>>(xch, xcl, pwh, pwl, pb, seq, yh, yl, nullptr, sw, 0);
  k_mixw <<<BB*NCH*64/256, 256>>>();
  k_tgemm<<<dim3(MM/128, 2), 256, SMEM_BYTES>>>(zh, zl, fwh, fwl, fb, seq, nullptr, nullptr, out, sw, 1);
}